// round 14
// baseline (speedup 1.0000x reference)
#include <cuda_runtime.h>
#include <cuda_bf16.h>
#include <cuda_fp16.h>
#include <cstdint>

#define NN 50000
#define EE 800000
#define IN_DIM 256
#define HID 128
#define OUT_DIM 64
#define NOFF (NN * OUT_DIM)

// ------------------------- device scratch -------------------------
__device__ int    g_count[NN];
__device__ int    g_cursor[NN];
__device__ int    g_offsets[NN + 1];
__device__ int    g_srclist[EE];
__device__ int    g_src[EE];
__device__ int    g_dst[EE];
__device__ float  g_dis[NN];
__device__ __half g_hw1h[NN * HID];   // fp16: dis[row] * (x @ W1^T)
__device__ __half g_hsh[NN * HID];    // fp16: dis * relu(agg1 + b1)
__device__ float  g_g[NN * HID];      // fp32: agg2 output (gemm2 input)
__device__ int    g_is64;

typedef unsigned long long ull;

// ------------------------- mma helpers -------------------------
__device__ __forceinline__ uint32_t smem_u32(const void* p) {
    uint32_t a;
    asm("{ .reg .u64 t; cvta.to.shared.u64 t, %1; cvt.u32.u64 %0, t; }" : "=r"(a) : "l"(p));
    return a;
}
__device__ __forceinline__ void ldsm_x4(uint32_t addr, uint32_t& r0, uint32_t& r1,
                                        uint32_t& r2, uint32_t& r3) {
    asm volatile("ldmatrix.sync.aligned.m8n8.x4.shared.b16 {%0,%1,%2,%3}, [%4];"
                 : "=r"(r0), "=r"(r1), "=r"(r2), "=r"(r3) : "r"(addr));
}
__device__ __forceinline__ void mma_bf16(float* d, uint32_t a0, uint32_t a1, uint32_t a2,
                                         uint32_t a3, uint32_t b0, uint32_t b1) {
    asm volatile(
        "mma.sync.aligned.m16n8k16.row.col.f32.bf16.bf16.f32 "
        "{%0,%1,%2,%3}, {%4,%5,%6,%7}, {%8,%9}, {%0,%1,%2,%3};"
        : "+f"(d[0]), "+f"(d[1]), "+f"(d[2]), "+f"(d[3])
        : "r"(a0), "r"(a1), "r"(a2), "r"(a3), "r"(b0), "r"(b1));
}
__device__ __forceinline__ uint32_t pack_bf16(float a, float b) {
    __nv_bfloat162 p = __floats2bfloat162_rn(a, b);
    return *reinterpret_cast<uint32_t*>(&p);
}
__device__ __forceinline__ float bf16_hi(float v) {
    return __bfloat162float(__float2bfloat16(v));
}

// ------------------------- small setup kernels -------------------------
__global__ void detect_kernel(const void* ei) {
    int lane = threadIdx.x;
    const long long* p = (const long long*)ei;
    int ok = 1;
    for (int i = lane; i < 1024; i += 32) {
        long long v = p[i];
        if (v < 0 || v >= NN) ok = 0;
    }
    unsigned m = __ballot_sync(0xffffffffu, ok);
    if (lane == 0) g_is64 = (m == 0xffffffffu) ? 1 : 0;
}

__global__ void convert_hist_kernel(const void* ei) {
    int i = blockIdx.x * blockDim.x + threadIdx.x;
    if (i >= EE) return;
    int s, d;
    if (g_is64) {
        const long long* p = (const long long*)ei;
        s = (int)p[i]; d = (int)p[EE + i];
    } else {
        const int* p = (const int*)ei;
        s = p[i]; d = p[EE + i];
    }
    s = min(max(s, 0), NN - 1);
    d = min(max(d, 0), NN - 1);
    g_src[i] = s; g_dst[i] = d;
    atomicAdd(&g_count[d], 1);
}

// scan: g_offsets (exclusive), g_cursor = offsets, g_dis = rsqrt(deg+1)
__global__ __launch_bounds__(1024) void scan_kernel() {
    const int T = 1024, PER = (NN + T - 1) / T;
    int tid = threadIdx.x;
    int base = tid * PER;
    int run = 0;
    for (int i = 0; i < PER; i++) { int idx = base + i; if (idx < NN) run += g_count[idx]; }
    __shared__ int wsum[32];
    int lane = tid & 31, wid = tid >> 5;
    int inc = run;
    for (int d = 1; d < 32; d <<= 1) {
        int t = __shfl_up_sync(0xffffffffu, inc, d);
        if (lane >= d) inc += t;
    }
    if (lane == 31) wsum[wid] = inc;
    __syncthreads();
    if (wid == 0) {
        int w = wsum[lane];
        for (int d = 1; d < 32; d <<= 1) {
            int t = __shfl_up_sync(0xffffffffu, w, d);
            if (lane >= d) w += t;
        }
        wsum[lane] = w;
    }
    __syncthreads();
    int warpbase = (wid == 0) ? 0 : wsum[wid - 1];
    int acc = warpbase + inc - run;
    for (int i = 0; i < PER; i++) {
        int idx = base + i;
        if (idx <= NN) {
            g_offsets[idx] = acc;
            if (idx < NN) {
                int c = g_count[idx];
                g_cursor[idx] = acc;
                g_dis[idx] = rsqrtf((float)(c + 1));
                acc += c;
            }
        }
    }
}

__global__ void scatter_kernel() {
    int i = blockIdx.x * blockDim.x + threadIdx.x;
    if (i >= EE) return;
    int d = g_dst[i];
    int pos = atomicAdd(&g_cursor[d], 1);
    g_srclist[pos] = g_src[i];
}

// ------------------------- GEMM1 via mma.sync bf16 hi/lo, 16 warps (R13) -------------
#define SROW 528
#define OFF_WHI 0
#define OFF_WLO 67584
#define OFF_XHI 135168
#define OFF_XLO 168960
#define G1_SMEM 202752

__global__ __launch_bounds__(512, 1)
void gemm1_mma_kernel(const float* __restrict__ x, const float* __restrict__ W1) {
    extern __shared__ char smc[];
    uint32_t su = smem_u32(smc);
    int tid = threadIdx.x, lane = tid & 31, warp = tid >> 5;
    int wr = warp & 3;
    int wc = warp >> 2;

#pragma unroll
    for (int it = 0; it < 16; it++) {
        int idx = it * 512 + tid;
        int o = idx >> 6, kq = idx & 63;
        float4 v = ((const float4*)W1)[o * 64 + kq];
        float hx = bf16_hi(v.x), hy = bf16_hi(v.y), hz = bf16_hi(v.z), hw = bf16_hi(v.w);
        uint2 hp = make_uint2(pack_bf16(hx, hy), pack_bf16(hz, hw));
        uint2 lp = make_uint2(pack_bf16(v.x - hx, v.y - hy), pack_bf16(v.z - hz, v.w - hw));
        *reinterpret_cast<uint2*>(smc + OFF_WHI + o * SROW + kq * 8) = hp;
        *reinterpret_cast<uint2*>(smc + OFF_WLO + o * SROW + kq * 8) = lp;
    }

    uint32_t a_off = (uint32_t)((wr * 16 + (lane & 15)) * SROW + ((lane >> 4) << 4));
    uint32_t b_row = (uint32_t)((lane & 7) + ((lane >> 4) << 3));
    uint32_t b_off = (uint32_t)((wc * 32 + b_row) * SROW + (((lane >> 3) & 1) << 4));

    const int NT = (NN + 63) / 64;
    for (int t = blockIdx.x; t < NT; t += gridDim.x) {
        int row0 = t * 64;
        __syncthreads();
#pragma unroll
        for (int it = 0; it < 8; it++) {
            int idx = it * 512 + tid;
            int r = idx >> 6, kq = idx & 63;
            int grow = row0 + r;
            float4 v = make_float4(0.f, 0.f, 0.f, 0.f);
            if (grow < NN) v = ((const float4*)x)[grow * 64 + kq];
            float hx = bf16_hi(v.x), hy = bf16_hi(v.y), hz = bf16_hi(v.z), hw = bf16_hi(v.w);
            uint2 hp = make_uint2(pack_bf16(hx, hy), pack_bf16(hz, hw));
            uint2 lp = make_uint2(pack_bf16(v.x - hx, v.y - hy), pack_bf16(v.z - hz, v.w - hw));
            *reinterpret_cast<uint2*>(smc + OFF_XHI + r * SROW + kq * 8) = hp;
            *reinterpret_cast<uint2*>(smc + OFF_XLO + r * SROW + kq * 8) = lp;
        }
        __syncthreads();

        float acc[4][4];
#pragma unroll
        for (int j = 0; j < 4; j++)
#pragma unroll
            for (int q = 0; q < 4; q++) acc[j][q] = 0.f;

        uint32_t ahb = su + OFF_XHI + a_off;
        uint32_t alb = su + OFF_XLO + a_off;
        uint32_t bhb = su + OFF_WHI + b_off;
        uint32_t blb = su + OFF_WLO + b_off;

#pragma unroll
        for (int ks = 0; ks < 16; ks++) {
            uint32_t ah0, ah1, ah2, ah3, al0, al1, al2, al3;
            ldsm_x4(ahb + ks * 32, ah0, ah1, ah2, ah3);
            ldsm_x4(alb + ks * 32, al0, al1, al2, al3);
#pragma unroll
            for (int j = 0; j < 2; j++) {
                uint32_t bh0, bh1, bh2, bh3, bl0, bl1, bl2, bl3;
                ldsm_x4(bhb + j * 16 * SROW + ks * 32, bh0, bh1, bh2, bh3);
                ldsm_x4(blb + j * 16 * SROW + ks * 32, bl0, bl1, bl2, bl3);
                mma_bf16(acc[2 * j],     ah0, ah1, ah2, ah3, bh0, bh1);
                mma_bf16(acc[2 * j + 1], ah0, ah1, ah2, ah3, bh2, bh3);
                mma_bf16(acc[2 * j],     al0, al1, al2, al3, bh0, bh1);
                mma_bf16(acc[2 * j + 1], al0, al1, al2, al3, bh2, bh3);
                mma_bf16(acc[2 * j],     ah0, ah1, ah2, ah3, bl0, bl1);
                mma_bf16(acc[2 * j + 1], ah0, ah1, ah2, ah3, bl2, bl3);
            }
        }

        int g = lane >> 2, tt = lane & 3;
        int r0g = row0 + wr * 16 + g;
        int r1g = r0g + 8;
        float di0 = (r0g < NN) ? g_dis[r0g] : 0.f;
        float di1 = (r1g < NN) ? g_dis[r1g] : 0.f;
#pragma unroll
        for (int j = 0; j < 4; j++) {
            int c = wc * 32 + j * 8 + 2 * tt;
            if (r0g < NN)
                *reinterpret_cast<__half2*>(g_hw1h + r0g * HID + c) =
                    __floats2half2_rn(di0 * acc[j][0], di0 * acc[j][1]);
            if (r1g < NN)
                *reinterpret_cast<__half2*>(g_hw1h + r1g * HID + c) =
                    __floats2half2_rn(di1 * acc[j][2], di1 * acc[j][3]);
        }
    }
}

// ------------------------- aggregation: warp per node, pipelined indices -------------
__device__ __forceinline__ float4 h4_to_f4(uint2 u) {
    __half2 a = *reinterpret_cast<__half2*>(&u.x);
    __half2 b = *reinterpret_cast<__half2*>(&u.y);
    float2 fa = __half22float2(a);
    float2 fb = __half22float2(b);
    return make_float4(fa.x, fa.y, fb.x, fb.y);
}

// gathers pairs with one pair of indices prefetched ahead; batch stays 2 (MLP discipline)
__device__ __forceinline__ float4 agg_gather(const uint2* __restrict__ f2, int gw, int lane) {
    int beg = g_offsets[gw], end = g_offsets[gw + 1];
    float4 acc = h4_to_f4(f2[gw * 32 + lane]);   // self-loop
    int p = beg;
    int s0 = 0, s1 = 0;
    bool have = false;
    if (p + 1 < end) { s0 = g_srclist[p]; s1 = g_srclist[p + 1]; p += 2; have = true; }
    while (p + 1 < end) {
        int n0 = g_srclist[p], n1 = g_srclist[p + 1];   // prefetch next pair
        p += 2;
        float4 v0 = h4_to_f4(f2[s0 * 32 + lane]);
        float4 v1 = h4_to_f4(f2[s1 * 32 + lane]);
        acc.x += v0.x; acc.y += v0.y; acc.z += v0.z; acc.w += v0.w;
        acc.x += v1.x; acc.y += v1.y; acc.z += v1.z; acc.w += v1.w;
        s0 = n0; s1 = n1;
    }
    if (have) {
        float4 v0 = h4_to_f4(f2[s0 * 32 + lane]);
        float4 v1 = h4_to_f4(f2[s1 * 32 + lane]);
        acc.x += v0.x; acc.y += v0.y; acc.z += v0.z; acc.w += v0.w;
        acc.x += v1.x; acc.y += v1.y; acc.z += v1.z; acc.w += v1.w;
    }
    if (p < end) {
        float4 v = h4_to_f4(f2[g_srclist[p] * 32 + lane]);
        acc.x += v.x; acc.y += v.y; acc.z += v.z; acc.w += v.w;
    }
    return acc;
}

__global__ __launch_bounds__(256) void agg1_kernel(const float* __restrict__ b1) {
    int gw = (blockIdx.x * blockDim.x + threadIdx.x) >> 5;
    int lane = threadIdx.x & 31;
    if (gw >= NN) return;
    float4 acc = agg_gather((const uint2*)g_hw1h, gw, lane);
    float di = g_dis[gw];
    float4 b = ((const float4*)b1)[lane];
    float rx = di * fmaxf(fmaf(di, acc.x, b.x), 0.f);
    float ry = di * fmaxf(fmaf(di, acc.y, b.y), 0.f);
    float rz = di * fmaxf(fmaf(di, acc.z, b.z), 0.f);
    float rw = di * fmaxf(fmaf(di, acc.w, b.w), 0.f);
    uint2 o;
    __half2 h0 = __floats2half2_rn(rx, ry);
    __half2 h1 = __floats2half2_rn(rz, rw);
    o.x = *reinterpret_cast<uint32_t*>(&h0);
    o.y = *reinterpret_cast<uint32_t*>(&h1);
    ((uint2*)g_hsh)[gw * 32 + lane] = o;
}

__global__ __launch_bounds__(256) void agg2_kernel() {
    int gw = (blockIdx.x * blockDim.x + threadIdx.x) >> 5;
    int lane = threadIdx.x & 31;
    if (gw >= NN) return;
    float4 acc = agg_gather((const uint2*)g_hsh, gw, lane);
    float di = g_dis[gw];
    float4 r = make_float4(di * acc.x, di * acc.y, di * acc.z, di * acc.w);
    ((float4*)g_g)[gw * 32 + lane] = r;
}

// ------------------------- GEMM2 via mma.sync bf16 hi/lo, fused passes (R12) ---------
#define SROW2 272
#define OFF2_WHI 0
#define OFF2_WLO 34816
#define OFF2_XHI 69632
#define OFF2_XLO 87040
#define OFF2_BIAS 104448
#define G2_SMEM 104960

__global__ __launch_bounds__(256, 2)
void gemm2_mma_kernel(const float* __restrict__ Wmu, const float* __restrict__ bmu,
                      const float* __restrict__ Wlv, const float* __restrict__ blv,
                      float* __restrict__ out) {
    extern __shared__ char smc[];
    uint32_t su = smem_u32(smc);
    int tid = threadIdx.x, lane = tid & 31, warp = tid >> 5;
    int wr = warp & 3;
    int wc = warp >> 2;

#pragma unroll
    for (int it = 0; it < 16; it++) {
        int idx = it * 256 + tid;
        int o = idx >> 5, kq = idx & 31;
        float4 v = (o < OUT_DIM) ? ((const float4*)Wmu)[o * 32 + kq]
                                 : ((const float4*)Wlv)[(o - OUT_DIM) * 32 + kq];
        float hx = bf16_hi(v.x), hy = bf16_hi(v.y), hz = bf16_hi(v.z), hw = bf16_hi(v.w);
        uint2 hp = make_uint2(pack_bf16(hx, hy), pack_bf16(hz, hw));
        uint2 lp = make_uint2(pack_bf16(v.x - hx, v.y - hy), pack_bf16(v.z - hz, v.w - hw));
        *reinterpret_cast<uint2*>(smc + OFF2_WHI + o * SROW2 + kq * 8) = hp;
        *reinterpret_cast<uint2*>(smc + OFF2_WLO + o * SROW2 + kq * 8) = lp;
    }
    if (tid < HID) {
        float b = (tid < OUT_DIM) ? bmu[tid] : blv[tid - OUT_DIM];
        *reinterpret_cast<float*>(smc + OFF2_BIAS + tid * 4) = b;
    }

    uint32_t a_off = (uint32_t)((wr * 16 + (lane & 15)) * SROW2 + ((lane >> 4) << 4));
    uint32_t b_row = (uint32_t)((lane & 7) + ((lane >> 4) << 3));
    uint32_t b_off = (uint32_t)((wc * 64 + b_row) * SROW2 + (((lane >> 3) & 1) << 4));

    const int NT = (NN + 63) / 64;
    for (int t = blockIdx.x; t < NT; t += gridDim.x) {
        int row0 = t * 64;
        __syncthreads();
#pragma unroll
        for (int it = 0; it < 8; it++) {
            int idx = it * 256 + tid;
            int r = idx >> 5, kq = idx & 31;
            int grow = row0 + r;
            float4 v = make_float4(0.f, 0.f, 0.f, 0.f);
            if (grow < NN) v = ((const float4*)g_g)[grow * 32 + kq];
            float hx = bf16_hi(v.x), hy = bf16_hi(v.y), hz = bf16_hi(v.z), hw = bf16_hi(v.w);
            uint2 hp = make_uint2(pack_bf16(hx, hy), pack_bf16(hz, hw));
            uint2 lp = make_uint2(pack_bf16(v.x - hx, v.y - hy), pack_bf16(v.z - hz, v.w - hw));
            *reinterpret_cast<uint2*>(smc + OFF2_XHI + r * SROW2 + kq * 8) = hp;
            *reinterpret_cast<uint2*>(smc + OFF2_XLO + r * SROW2 + kq * 8) = lp;
        }
        __syncthreads();

        float acc[8][4];
#pragma unroll
        for (int j = 0; j < 8; j++)
#pragma unroll
            for (int q = 0; q < 4; q++) acc[j][q] = 0.f;

        uint32_t ahb = su + OFF2_XHI + a_off;
        uint32_t alb = su + OFF2_XLO + a_off;
        uint32_t bhb = su + OFF2_WHI + b_off;
        uint32_t blb = su + OFF2_WLO + b_off;

#pragma unroll
        for (int ks = 0; ks < 8; ks++) {
            uint32_t ah0, ah1, ah2, ah3, al0, al1, al2, al3;
            ldsm_x4(ahb + ks * 32, ah0, ah1, ah2, ah3);
            ldsm_x4(alb + ks * 32, al0, al1, al2, al3);
#pragma unroll
            for (int j = 0; j < 4; j++) {
                uint32_t bh0, bh1, bh2, bh3, bl0, bl1, bl2, bl3;
                ldsm_x4(bhb + j * 16 * SROW2 + ks * 32, bh0, bh1, bh2, bh3);
                ldsm_x4(blb + j * 16 * SROW2 + ks * 32, bl0, bl1, bl2, bl3);
                mma_bf16(acc[2 * j],     ah0, ah1, ah2, ah3, bh0, bh1);
                mma_bf16(acc[2 * j + 1], ah0, ah1, ah2, ah3, bh2, bh3);
                mma_bf16(acc[2 * j],     al0, al1, al2, al3, bh0, bh1);
                mma_bf16(acc[2 * j + 1], al0, al1, al2, al3, bh2, bh3);
                mma_bf16(acc[2 * j],     ah0, ah1, ah2, ah3, bl0, bl1);
                mma_bf16(acc[2 * j + 1], ah0, ah1, ah2, ah3, bl2, bl3);
            }
        }

        int g = lane >> 2, tt = lane & 3;
        int r0g = row0 + wr * 16 + g;
        int r1g = r0g + 8;
        float* obase = (wc == 0) ? out : (out + NOFF);
#pragma unroll
        for (int j = 0; j < 8; j++) {
            int cl = j * 8 + 2 * tt;
            float2 bv = *reinterpret_cast<float2*>(smc + OFF2_BIAS + (wc * 64 + cl) * 4);
            if (r0g < NN)
                *reinterpret_cast<float2*>(obase + r0g * OUT_DIM + cl) =
                    make_float2(acc[j][0] + bv.x, acc[j][1] + bv.y);
            if (r1g < NN)
                *reinterpret_cast<float2*>(obase + r1g * OUT_DIM + cl) =
                    make_float2(acc[j][2] + bv.x, acc[j][3] + bv.y);
        }
    }
}

// ------------------------- launch -------------------------
extern "C" void kernel_launch(void* const* d_in, const int* in_sizes, int n_in,
                              void* d_out, int out_size) {
    const float* x   = (const float*)d_in[0];
    const void*  ei  = d_in[1];
    const float* W1  = (const float*)d_in[2];
    const float* b1  = (const float*)d_in[3];
    const float* Wmu = (const float*)d_in[4];
    const float* bmu = (const float*)d_in[5];
    const float* Wlv = (const float*)d_in[6];
    const float* blv = (const float*)d_in[7];
    float* out = (float*)d_out;

    void* p_count; cudaGetSymbolAddress(&p_count, g_count);

    cudaFuncSetAttribute(gemm1_mma_kernel, cudaFuncAttributeMaxDynamicSharedMemorySize, G1_SMEM);
    cudaFuncSetAttribute(gemm2_mma_kernel, cudaFuncAttributeMaxDynamicSharedMemorySize, G2_SMEM);

    cudaMemsetAsync(p_count, 0, NN * sizeof(int));

    detect_kernel<<<1, 32>>>(ei);                                // #1
    convert_hist_kernel<<<(EE + 255) / 256, 256>>>(ei);          // #2
    scan_kernel<<<1, 1024>>>();                                  // #3  offsets+cursor+dis

    gemm1_mma_kernel<<<148, 512, G1_SMEM>>>(x, W1);              // #4  <- profiled

    scatter_kernel<<<(EE + 255) / 256, 256>>>();                 // #5

    int agg_blocks = (NN * 32 + 255) / 256;
    agg1_kernel<<<agg_blocks, 256>>>(b1);                        // #6
    agg2_kernel<<<agg_blocks, 256>>>();                          // #7

    gemm2_mma_kernel<<<296, 256, G2_SMEM>>>(Wmu, bmu, Wlv, blv, out);  // #8
}

// round 15
// speedup vs baseline: 1.0329x; 1.0329x over previous
#include <cuda_runtime.h>
#include <cuda_bf16.h>
#include <cuda_fp16.h>
#include <cstdint>

#define NN 50000
#define EE 800000
#define IN_DIM 256
#define HID 128
#define OUT_DIM 64
#define NOFF (NN * OUT_DIM)

// ------------------------- device scratch -------------------------
__device__ int    g_count[NN];
__device__ int    g_cursor[NN];
__device__ int    g_offsets[NN + 1];
__device__ int    g_srclist[EE];
__device__ int    g_src[EE];
__device__ int    g_dst[EE];
__device__ float  g_dis[NN];
__device__ __half g_hw1h[NN * HID];   // fp16: dis[row] * (x @ W1^T)
__device__ __half g_hsh[NN * HID];    // fp16: dis * relu(agg1 + b1)
__device__ float  g_g[NN * HID];      // fp32: agg2 output (gemm2 input)
__device__ int    g_is64;

typedef unsigned long long ull;

// ------------------------- mma helpers -------------------------
__device__ __forceinline__ uint32_t smem_u32(const void* p) {
    uint32_t a;
    asm("{ .reg .u64 t; cvta.to.shared.u64 t, %1; cvt.u32.u64 %0, t; }" : "=r"(a) : "l"(p));
    return a;
}
__device__ __forceinline__ void ldsm_x4(uint32_t addr, uint32_t& r0, uint32_t& r1,
                                        uint32_t& r2, uint32_t& r3) {
    asm volatile("ldmatrix.sync.aligned.m8n8.x4.shared.b16 {%0,%1,%2,%3}, [%4];"
                 : "=r"(r0), "=r"(r1), "=r"(r2), "=r"(r3) : "r"(addr));
}
__device__ __forceinline__ void mma_bf16(float* d, uint32_t a0, uint32_t a1, uint32_t a2,
                                         uint32_t a3, uint32_t b0, uint32_t b1) {
    asm volatile(
        "mma.sync.aligned.m16n8k16.row.col.f32.bf16.bf16.f32 "
        "{%0,%1,%2,%3}, {%4,%5,%6,%7}, {%8,%9}, {%0,%1,%2,%3};"
        : "+f"(d[0]), "+f"(d[1]), "+f"(d[2]), "+f"(d[3])
        : "r"(a0), "r"(a1), "r"(a2), "r"(a3), "r"(b0), "r"(b1));
}
__device__ __forceinline__ uint32_t pack_bf16(float a, float b) {
    __nv_bfloat162 p = __floats2bfloat162_rn(a, b);
    return *reinterpret_cast<uint32_t*>(&p);
}
__device__ __forceinline__ float bf16_hi(float v) {
    return __bfloat162float(__float2bfloat16(v));
}

// ------------------------- small setup kernels -------------------------
__global__ void detect_kernel(const void* ei) {
    int lane = threadIdx.x;
    const long long* p = (const long long*)ei;
    int ok = 1;
    for (int i = lane; i < 1024; i += 32) {
        long long v = p[i];
        if (v < 0 || v >= NN) ok = 0;
    }
    unsigned m = __ballot_sync(0xffffffffu, ok);
    if (lane == 0) g_is64 = (m == 0xffffffffu) ? 1 : 0;
}

__global__ void convert_hist_kernel(const void* ei) {
    int i = blockIdx.x * blockDim.x + threadIdx.x;
    if (i >= EE) return;
    int s, d;
    if (g_is64) {
        const long long* p = (const long long*)ei;
        s = (int)p[i]; d = (int)p[EE + i];
    } else {
        const int* p = (const int*)ei;
        s = p[i]; d = p[EE + i];
    }
    s = min(max(s, 0), NN - 1);
    d = min(max(d, 0), NN - 1);
    g_src[i] = s; g_dst[i] = d;
    atomicAdd(&g_count[d], 1);
}

// fused scan: g_offsets (exclusive), g_cursor = offsets, g_dis = rsqrt(deg+1)
__global__ __launch_bounds__(1024) void scan_kernel() {
    const int T = 1024, PER = (NN + T - 1) / T;
    int tid = threadIdx.x;
    int base = tid * PER;
    int run = 0;
    for (int i = 0; i < PER; i++) { int idx = base + i; if (idx < NN) run += g_count[idx]; }
    __shared__ int wsum[32];
    int lane = tid & 31, wid = tid >> 5;
    int inc = run;
    for (int d = 1; d < 32; d <<= 1) {
        int t = __shfl_up_sync(0xffffffffu, inc, d);
        if (lane >= d) inc += t;
    }
    if (lane == 31) wsum[wid] = inc;
    __syncthreads();
    if (wid == 0) {
        int w = wsum[lane];
        for (int d = 1; d < 32; d <<= 1) {
            int t = __shfl_up_sync(0xffffffffu, w, d);
            if (lane >= d) w += t;
        }
        wsum[lane] = w;
    }
    __syncthreads();
    int warpbase = (wid == 0) ? 0 : wsum[wid - 1];
    int acc = warpbase + inc - run;
    for (int i = 0; i < PER; i++) {
        int idx = base + i;
        if (idx <= NN) {
            g_offsets[idx] = acc;
            if (idx < NN) {
                int c = g_count[idx];
                g_cursor[idx] = acc;
                g_dis[idx] = rsqrtf((float)(c + 1));
                acc += c;
            }
        }
    }
}

__global__ void scatter_kernel() {
    int i = blockIdx.x * blockDim.x + threadIdx.x;
    if (i >= EE) return;
    int d = g_dst[i];
    int pos = atomicAdd(&g_cursor[d], 1);
    g_srclist[pos] = g_src[i];
}

// ------------------------- GEMM1 via mma.sync bf16 hi/lo, 16 warps (R13) -------------
#define SROW 528
#define OFF_WHI 0
#define OFF_WLO 67584
#define OFF_XHI 135168
#define OFF_XLO 168960
#define G1_SMEM 202752

__global__ __launch_bounds__(512, 1)
void gemm1_mma_kernel(const float* __restrict__ x, const float* __restrict__ W1) {
    extern __shared__ char smc[];
    uint32_t su = smem_u32(smc);
    int tid = threadIdx.x, lane = tid & 31, warp = tid >> 5;
    int wr = warp & 3;
    int wc = warp >> 2;

#pragma unroll
    for (int it = 0; it < 16; it++) {
        int idx = it * 512 + tid;
        int o = idx >> 6, kq = idx & 63;
        float4 v = ((const float4*)W1)[o * 64 + kq];
        float hx = bf16_hi(v.x), hy = bf16_hi(v.y), hz = bf16_hi(v.z), hw = bf16_hi(v.w);
        uint2 hp = make_uint2(pack_bf16(hx, hy), pack_bf16(hz, hw));
        uint2 lp = make_uint2(pack_bf16(v.x - hx, v.y - hy), pack_bf16(v.z - hz, v.w - hw));
        *reinterpret_cast<uint2*>(smc + OFF_WHI + o * SROW + kq * 8) = hp;
        *reinterpret_cast<uint2*>(smc + OFF_WLO + o * SROW + kq * 8) = lp;
    }

    uint32_t a_off = (uint32_t)((wr * 16 + (lane & 15)) * SROW + ((lane >> 4) << 4));
    uint32_t b_row = (uint32_t)((lane & 7) + ((lane >> 4) << 3));
    uint32_t b_off = (uint32_t)((wc * 32 + b_row) * SROW + (((lane >> 3) & 1) << 4));

    const int NT = (NN + 63) / 64;
    for (int t = blockIdx.x; t < NT; t += gridDim.x) {
        int row0 = t * 64;
        __syncthreads();
#pragma unroll
        for (int it = 0; it < 8; it++) {
            int idx = it * 512 + tid;
            int r = idx >> 6, kq = idx & 63;
            int grow = row0 + r;
            float4 v = make_float4(0.f, 0.f, 0.f, 0.f);
            if (grow < NN) v = ((const float4*)x)[grow * 64 + kq];
            float hx = bf16_hi(v.x), hy = bf16_hi(v.y), hz = bf16_hi(v.z), hw = bf16_hi(v.w);
            uint2 hp = make_uint2(pack_bf16(hx, hy), pack_bf16(hz, hw));
            uint2 lp = make_uint2(pack_bf16(v.x - hx, v.y - hy), pack_bf16(v.z - hz, v.w - hw));
            *reinterpret_cast<uint2*>(smc + OFF_XHI + r * SROW + kq * 8) = hp;
            *reinterpret_cast<uint2*>(smc + OFF_XLO + r * SROW + kq * 8) = lp;
        }
        __syncthreads();

        float acc[4][4];
#pragma unroll
        for (int j = 0; j < 4; j++)
#pragma unroll
            for (int q = 0; q < 4; q++) acc[j][q] = 0.f;

        uint32_t ahb = su + OFF_XHI + a_off;
        uint32_t alb = su + OFF_XLO + a_off;
        uint32_t bhb = su + OFF_WHI + b_off;
        uint32_t blb = su + OFF_WLO + b_off;

#pragma unroll
        for (int ks = 0; ks < 16; ks++) {
            uint32_t ah0, ah1, ah2, ah3, al0, al1, al2, al3;
            ldsm_x4(ahb + ks * 32, ah0, ah1, ah2, ah3);
            ldsm_x4(alb + ks * 32, al0, al1, al2, al3);
#pragma unroll
            for (int j = 0; j < 2; j++) {
                uint32_t bh0, bh1, bh2, bh3, bl0, bl1, bl2, bl3;
                ldsm_x4(bhb + j * 16 * SROW + ks * 32, bh0, bh1, bh2, bh3);
                ldsm_x4(blb + j * 16 * SROW + ks * 32, bl0, bl1, bl2, bl3);
                mma_bf16(acc[2 * j],     ah0, ah1, ah2, ah3, bh0, bh1);
                mma_bf16(acc[2 * j + 1], ah0, ah1, ah2, ah3, bh2, bh3);
                mma_bf16(acc[2 * j],     al0, al1, al2, al3, bh0, bh1);
                mma_bf16(acc[2 * j + 1], al0, al1, al2, al3, bh2, bh3);
                mma_bf16(acc[2 * j],     ah0, ah1, ah2, ah3, bl0, bl1);
                mma_bf16(acc[2 * j + 1], ah0, ah1, ah2, ah3, bl2, bl3);
            }
        }

        int g = lane >> 2, tt = lane & 3;
        int r0g = row0 + wr * 16 + g;
        int r1g = r0g + 8;
        float di0 = (r0g < NN) ? g_dis[r0g] : 0.f;
        float di1 = (r1g < NN) ? g_dis[r1g] : 0.f;
#pragma unroll
        for (int j = 0; j < 4; j++) {
            int c = wc * 32 + j * 8 + 2 * tt;
            if (r0g < NN)
                *reinterpret_cast<__half2*>(g_hw1h + r0g * HID + c) =
                    __floats2half2_rn(di0 * acc[j][0], di0 * acc[j][1]);
            if (r1g < NN)
                *reinterpret_cast<__half2*>(g_hw1h + r1g * HID + c) =
                    __floats2half2_rn(di1 * acc[j][2], di1 * acc[j][3]);
        }
    }
}

// ------------------------- aggregation: warp per node (R13 exact bodies) -------------
__device__ __forceinline__ float4 h4_to_f4(uint2 u) {
    __half2 a = *reinterpret_cast<__half2*>(&u.x);
    __half2 b = *reinterpret_cast<__half2*>(&u.y);
    float2 fa = __half22float2(a);
    float2 fb = __half22float2(b);
    return make_float4(fa.x, fa.y, fb.x, fb.y);
}

__global__ __launch_bounds__(256) void agg1_kernel(const float* __restrict__ b1) {
    int gw = (blockIdx.x * blockDim.x + threadIdx.x) >> 5;
    int lane = threadIdx.x & 31;
    if (gw >= NN) return;
    int beg = g_offsets[gw], end = g_offsets[gw + 1];
    const uint2* f2 = (const uint2*)g_hw1h;
    float4 acc = h4_to_f4(f2[gw * 32 + lane]);
    int p = beg;
    for (; p + 1 < end; p += 2) {
        int s0 = g_srclist[p], s1 = g_srclist[p + 1];
        float4 v0 = h4_to_f4(f2[s0 * 32 + lane]);
        float4 v1 = h4_to_f4(f2[s1 * 32 + lane]);
        acc.x += v0.x; acc.y += v0.y; acc.z += v0.z; acc.w += v0.w;
        acc.x += v1.x; acc.y += v1.y; acc.z += v1.z; acc.w += v1.w;
    }
    if (p < end) {
        float4 v = h4_to_f4(f2[g_srclist[p] * 32 + lane]);
        acc.x += v.x; acc.y += v.y; acc.z += v.z; acc.w += v.w;
    }
    float di = g_dis[gw];
    float4 b = ((const float4*)b1)[lane];
    float rx = di * fmaxf(fmaf(di, acc.x, b.x), 0.f);
    float ry = di * fmaxf(fmaf(di, acc.y, b.y), 0.f);
    float rz = di * fmaxf(fmaf(di, acc.z, b.z), 0.f);
    float rw = di * fmaxf(fmaf(di, acc.w, b.w), 0.f);
    uint2 o;
    __half2 h0 = __floats2half2_rn(rx, ry);
    __half2 h1 = __floats2half2_rn(rz, rw);
    o.x = *reinterpret_cast<uint32_t*>(&h0);
    o.y = *reinterpret_cast<uint32_t*>(&h1);
    ((uint2*)g_hsh)[gw * 32 + lane] = o;
}

__global__ __launch_bounds__(256) void agg2_kernel() {
    int gw = (blockIdx.x * blockDim.x + threadIdx.x) >> 5;
    int lane = threadIdx.x & 31;
    if (gw >= NN) return;
    int beg = g_offsets[gw], end = g_offsets[gw + 1];
    const uint2* f2 = (const uint2*)g_hsh;
    float4 acc = h4_to_f4(f2[gw * 32 + lane]);
    int p = beg;
    for (; p + 1 < end; p += 2) {
        int s0 = g_srclist[p], s1 = g_srclist[p + 1];
        float4 v0 = h4_to_f4(f2[s0 * 32 + lane]);
        float4 v1 = h4_to_f4(f2[s1 * 32 + lane]);
        acc.x += v0.x; acc.y += v0.y; acc.z += v0.z; acc.w += v0.w;
        acc.x += v1.x; acc.y += v1.y; acc.z += v1.z; acc.w += v1.w;
    }
    if (p < end) {
        float4 v = h4_to_f4(f2[g_srclist[p] * 32 + lane]);
        acc.x += v.x; acc.y += v.y; acc.z += v.z; acc.w += v.w;
    }
    float di = g_dis[gw];
    float4 r = make_float4(di * acc.x, di * acc.y, di * acc.z, di * acc.w);
    ((float4*)g_g)[gw * 32 + lane] = r;
}

// ------------------------- GEMM2 via mma.sync bf16 hi/lo, fused passes (R12) ---------
#define SROW2 272
#define OFF2_WHI 0
#define OFF2_WLO 34816
#define OFF2_XHI 69632
#define OFF2_XLO 87040
#define OFF2_BIAS 104448
#define G2_SMEM 104960

__global__ __launch_bounds__(256, 2)
void gemm2_mma_kernel(const float* __restrict__ Wmu, const float* __restrict__ bmu,
                      const float* __restrict__ Wlv, const float* __restrict__ blv,
                      float* __restrict__ out) {
    extern __shared__ char smc[];
    uint32_t su = smem_u32(smc);
    int tid = threadIdx.x, lane = tid & 31, warp = tid >> 5;
    int wr = warp & 3;
    int wc = warp >> 2;

#pragma unroll
    for (int it = 0; it < 16; it++) {
        int idx = it * 256 + tid;
        int o = idx >> 5, kq = idx & 31;
        float4 v = (o < OUT_DIM) ? ((const float4*)Wmu)[o * 32 + kq]
                                 : ((const float4*)Wlv)[(o - OUT_DIM) * 32 + kq];
        float hx = bf16_hi(v.x), hy = bf16_hi(v.y), hz = bf16_hi(v.z), hw = bf16_hi(v.w);
        uint2 hp = make_uint2(pack_bf16(hx, hy), pack_bf16(hz, hw));
        uint2 lp = make_uint2(pack_bf16(v.x - hx, v.y - hy), pack_bf16(v.z - hz, v.w - hw));
        *reinterpret_cast<uint2*>(smc + OFF2_WHI + o * SROW2 + kq * 8) = hp;
        *reinterpret_cast<uint2*>(smc + OFF2_WLO + o * SROW2 + kq * 8) = lp;
    }
    if (tid < HID) {
        float b = (tid < OUT_DIM) ? bmu[tid] : blv[tid - OUT_DIM];
        *reinterpret_cast<float*>(smc + OFF2_BIAS + tid * 4) = b;
    }

    uint32_t a_off = (uint32_t)((wr * 16 + (lane & 15)) * SROW2 + ((lane >> 4) << 4));
    uint32_t b_row = (uint32_t)((lane & 7) + ((lane >> 4) << 3));
    uint32_t b_off = (uint32_t)((wc * 64 + b_row) * SROW2 + (((lane >> 3) & 1) << 4));

    const int NT = (NN + 63) / 64;
    for (int t = blockIdx.x; t < NT; t += gridDim.x) {
        int row0 = t * 64;
        __syncthreads();
#pragma unroll
        for (int it = 0; it < 8; it++) {
            int idx = it * 256 + tid;
            int r = idx >> 5, kq = idx & 31;
            int grow = row0 + r;
            float4 v = make_float4(0.f, 0.f, 0.f, 0.f);
            if (grow < NN) v = ((const float4*)g_g)[grow * 32 + kq];
            float hx = bf16_hi(v.x), hy = bf16_hi(v.y), hz = bf16_hi(v.z), hw = bf16_hi(v.w);
            uint2 hp = make_uint2(pack_bf16(hx, hy), pack_bf16(hz, hw));
            uint2 lp = make_uint2(pack_bf16(v.x - hx, v.y - hy), pack_bf16(v.z - hz, v.w - hw));
            *reinterpret_cast<uint2*>(smc + OFF2_XHI + r * SROW2 + kq * 8) = hp;
            *reinterpret_cast<uint2*>(smc + OFF2_XLO + r * SROW2 + kq * 8) = lp;
        }
        __syncthreads();

        float acc[8][4];
#pragma unroll
        for (int j = 0; j < 8; j++)
#pragma unroll
            for (int q = 0; q < 4; q++) acc[j][q] = 0.f;

        uint32_t ahb = su + OFF2_XHI + a_off;
        uint32_t alb = su + OFF2_XLO + a_off;
        uint32_t bhb = su + OFF2_WHI + b_off;
        uint32_t blb = su + OFF2_WLO + b_off;

#pragma unroll
        for (int ks = 0; ks < 8; ks++) {
            uint32_t ah0, ah1, ah2, ah3, al0, al1, al2, al3;
            ldsm_x4(ahb + ks * 32, ah0, ah1, ah2, ah3);
            ldsm_x4(alb + ks * 32, al0, al1, al2, al3);
#pragma unroll
            for (int j = 0; j < 4; j++) {
                uint32_t bh0, bh1, bh2, bh3, bl0, bl1, bl2, bl3;
                ldsm_x4(bhb + j * 16 * SROW2 + ks * 32, bh0, bh1, bh2, bh3);
                ldsm_x4(blb + j * 16 * SROW2 + ks * 32, bl0, bl1, bl2, bl3);
                mma_bf16(acc[2 * j],     ah0, ah1, ah2, ah3, bh0, bh1);
                mma_bf16(acc[2 * j + 1], ah0, ah1, ah2, ah3, bh2, bh3);
                mma_bf16(acc[2 * j],     al0, al1, al2, al3, bh0, bh1);
                mma_bf16(acc[2 * j + 1], al0, al1, al2, al3, bh2, bh3);
                mma_bf16(acc[2 * j],     ah0, ah1, ah2, ah3, bl0, bl1);
                mma_bf16(acc[2 * j + 1], ah0, ah1, ah2, ah3, bl2, bl3);
            }
        }

        int g = lane >> 2, tt = lane & 3;
        int r0g = row0 + wr * 16 + g;
        int r1g = r0g + 8;
        float* obase = (wc == 0) ? out : (out + NOFF);
#pragma unroll
        for (int j = 0; j < 8; j++) {
            int cl = j * 8 + 2 * tt;
            float2 bv = *reinterpret_cast<float2*>(smc + OFF2_BIAS + (wc * 64 + cl) * 4);
            if (r0g < NN)
                *reinterpret_cast<float2*>(obase + r0g * OUT_DIM + cl) =
                    make_float2(acc[j][0] + bv.x, acc[j][1] + bv.y);
            if (r1g < NN)
                *reinterpret_cast<float2*>(obase + r1g * OUT_DIM + cl) =
                    make_float2(acc[j][2] + bv.x, acc[j][3] + bv.y);
        }
    }
}

// ------------------------- launch -------------------------
extern "C" void kernel_launch(void* const* d_in, const int* in_sizes, int n_in,
                              void* d_out, int out_size) {
    const float* x   = (const float*)d_in[0];
    const void*  ei  = d_in[1];
    const float* W1  = (const float*)d_in[2];
    const float* b1  = (const float*)d_in[3];
    const float* Wmu = (const float*)d_in[4];
    const float* bmu = (const float*)d_in[5];
    const float* Wlv = (const float*)d_in[6];
    const float* blv = (const float*)d_in[7];
    float* out = (float*)d_out;

    void* p_count; cudaGetSymbolAddress(&p_count, g_count);

    cudaFuncSetAttribute(gemm1_mma_kernel, cudaFuncAttributeMaxDynamicSharedMemorySize, G1_SMEM);
    cudaFuncSetAttribute(gemm2_mma_kernel, cudaFuncAttributeMaxDynamicSharedMemorySize, G2_SMEM);

    cudaMemsetAsync(p_count, 0, NN * sizeof(int));

    detect_kernel<<<1, 32>>>(ei);                                // #1
    convert_hist_kernel<<<(EE + 255) / 256, 256>>>(ei);          // #2
    scan_kernel<<<1, 1024>>>();                                  // #3  offsets+cursor+dis

    gemm1_mma_kernel<<<148, 512, G1_SMEM>>>(x, W1);              // #4  <- profiled

    scatter_kernel<<<(EE + 255) / 256, 256>>>();                 // #5

    int agg_blocks = (NN * 32 + 255) / 256;
    agg1_kernel<<<agg_blocks, 256>>>(b1);                        // #6
    agg2_kernel<<<agg_blocks, 256>>>();                          // #7

    gemm2_mma_kernel<<<296, 256, G2_SMEM>>>(Wmu, bmu, Wlv, blv, out);  // #8
}

// round 16
// speedup vs baseline: 1.3342x; 1.2916x over previous
#include <cuda_runtime.h>
#include <cuda_bf16.h>
#include <cuda_fp16.h>
#include <cstdint>

#define NN 50000
#define EE 800000
#define IN_DIM 256
#define HID 128
#define OUT_DIM 64
#define NOFF (NN * OUT_DIM)

// ------------------------- device scratch -------------------------
__device__ int    g_count[NN];
__device__ int    g_cursor[NN];
__device__ int    g_offsets[NN + 1];
__device__ int    g_srclist[EE];
__device__ int    g_src[EE];
__device__ int    g_dst[EE];
__device__ float  g_dis[NN];
__device__ __half g_hw1h[NN * HID];   // fp16: dis[row] * (x @ W1^T)
__device__ __half g_hsh[NN * HID];    // fp16: dis * relu(agg1 + b1)
__device__ __half g_gh[NN * HID];     // fp16: agg2 output (gemm2 input)
__device__ int    g_is64;

typedef unsigned long long ull;

// ------------------------- mma helpers -------------------------
__device__ __forceinline__ uint32_t smem_u32(const void* p) {
    uint32_t a;
    asm("{ .reg .u64 t; cvta.to.shared.u64 t, %1; cvt.u32.u64 %0, t; }" : "=r"(a) : "l"(p));
    return a;
}
__device__ __forceinline__ void ldsm_x4(uint32_t addr, uint32_t& r0, uint32_t& r1,
                                        uint32_t& r2, uint32_t& r3) {
    asm volatile("ldmatrix.sync.aligned.m8n8.x4.shared.b16 {%0,%1,%2,%3}, [%4];"
                 : "=r"(r0), "=r"(r1), "=r"(r2), "=r"(r3) : "r"(addr));
}
__device__ __forceinline__ void mma_bf16(float* d, uint32_t a0, uint32_t a1, uint32_t a2,
                                         uint32_t a3, uint32_t b0, uint32_t b1) {
    asm volatile(
        "mma.sync.aligned.m16n8k16.row.col.f32.bf16.bf16.f32 "
        "{%0,%1,%2,%3}, {%4,%5,%6,%7}, {%8,%9}, {%0,%1,%2,%3};"
        : "+f"(d[0]), "+f"(d[1]), "+f"(d[2]), "+f"(d[3])
        : "r"(a0), "r"(a1), "r"(a2), "r"(a3), "r"(b0), "r"(b1));
}
__device__ __forceinline__ uint32_t pack_bf16(float a, float b) {
    __nv_bfloat162 p = __floats2bfloat162_rn(a, b);
    return *reinterpret_cast<uint32_t*>(&p);
}
__device__ __forceinline__ float bf16_hi(float v) {
    return __bfloat162float(__float2bfloat16(v));
}

// ------------------------- small setup kernels -------------------------
__global__ void detect_kernel(const void* ei) {
    int lane = threadIdx.x;
    const long long* p = (const long long*)ei;
    int ok = 1;
    for (int i = lane; i < 1024; i += 32) {
        long long v = p[i];
        if (v < 0 || v >= NN) ok = 0;
    }
    unsigned m = __ballot_sync(0xffffffffu, ok);
    if (lane == 0) g_is64 = (m == 0xffffffffu) ? 1 : 0;
}

__global__ void convert_hist_kernel(const void* ei) {
    int i = blockIdx.x * blockDim.x + threadIdx.x;
    if (i >= EE) return;
    int s, d;
    if (g_is64) {
        const long long* p = (const long long*)ei;
        s = (int)p[i]; d = (int)p[EE + i];
    } else {
        const int* p = (const int*)ei;
        s = p[i]; d = p[EE + i];
    }
    s = min(max(s, 0), NN - 1);
    d = min(max(d, 0), NN - 1);
    g_src[i] = s; g_dst[i] = d;
    atomicAdd(&g_count[d], 1);
}

// wide dis kernel — MUFU spread across many SMs (single-block version is ~50us: banned)
__global__ void dis_kernel() {
    int i = blockIdx.x * blockDim.x + threadIdx.x;
    if (i < NN) g_dis[i] = rsqrtf((float)(g_count[i] + 1));
}

__global__ __launch_bounds__(1024) void scan_kernel() {
    const int T = 1024, PER = (NN + T - 1) / T;
    int tid = threadIdx.x;
    int base = tid * PER;
    int run = 0;
    for (int i = 0; i < PER; i++) { int idx = base + i; if (idx < NN) run += g_count[idx]; }
    __shared__ int wsum[32];
    int lane = tid & 31, wid = tid >> 5;
    int inc = run;
    for (int d = 1; d < 32; d <<= 1) {
        int t = __shfl_up_sync(0xffffffffu, inc, d);
        if (lane >= d) inc += t;
    }
    if (lane == 31) wsum[wid] = inc;
    __syncthreads();
    if (wid == 0) {
        int w = wsum[lane];
        for (int d = 1; d < 32; d <<= 1) {
            int t = __shfl_up_sync(0xffffffffu, w, d);
            if (lane >= d) w += t;
        }
        wsum[lane] = w;
    }
    __syncthreads();
    int warpbase = (wid == 0) ? 0 : wsum[wid - 1];
    int acc = warpbase + inc - run;
    for (int i = 0; i < PER; i++) {
        int idx = base + i;
        if (idx <= NN) {
            g_offsets[idx] = acc;
            if (idx < NN) acc += g_count[idx];
        }
    }
}

__global__ void scatter_kernel() {
    int i = blockIdx.x * blockDim.x + threadIdx.x;
    if (i >= EE) return;
    int d = g_dst[i];
    int pos = g_offsets[d] + atomicAdd(&g_cursor[d], 1);
    g_srclist[pos] = g_src[i];
}

// ------------------------- GEMM1 via mma.sync bf16 hi/lo, 16 warps (R13) -------------
#define SROW 528
#define OFF_WHI 0
#define OFF_WLO 67584
#define OFF_XHI 135168
#define OFF_XLO 168960
#define G1_SMEM 202752

__global__ __launch_bounds__(512, 1)
void gemm1_mma_kernel(const float* __restrict__ x, const float* __restrict__ W1) {
    extern __shared__ char smc[];
    uint32_t su = smem_u32(smc);
    int tid = threadIdx.x, lane = tid & 31, warp = tid >> 5;
    int wr = warp & 3;
    int wc = warp >> 2;

#pragma unroll
    for (int it = 0; it < 16; it++) {
        int idx = it * 512 + tid;
        int o = idx >> 6, kq = idx & 63;
        float4 v = ((const float4*)W1)[o * 64 + kq];
        float hx = bf16_hi(v.x), hy = bf16_hi(v.y), hz = bf16_hi(v.z), hw = bf16_hi(v.w);
        uint2 hp = make_uint2(pack_bf16(hx, hy), pack_bf16(hz, hw));
        uint2 lp = make_uint2(pack_bf16(v.x - hx, v.y - hy), pack_bf16(v.z - hz, v.w - hw));
        *reinterpret_cast<uint2*>(smc + OFF_WHI + o * SROW + kq * 8) = hp;
        *reinterpret_cast<uint2*>(smc + OFF_WLO + o * SROW + kq * 8) = lp;
    }

    uint32_t a_off = (uint32_t)((wr * 16 + (lane & 15)) * SROW + ((lane >> 4) << 4));
    uint32_t b_row = (uint32_t)((lane & 7) + ((lane >> 4) << 3));
    uint32_t b_off = (uint32_t)((wc * 32 + b_row) * SROW + (((lane >> 3) & 1) << 4));

    const int NT = (NN + 63) / 64;
    for (int t = blockIdx.x; t < NT; t += gridDim.x) {
        int row0 = t * 64;
        __syncthreads();
#pragma unroll
        for (int it = 0; it < 8; it++) {
            int idx = it * 512 + tid;
            int r = idx >> 6, kq = idx & 63;
            int grow = row0 + r;
            float4 v = make_float4(0.f, 0.f, 0.f, 0.f);
            if (grow < NN) v = ((const float4*)x)[grow * 64 + kq];
            float hx = bf16_hi(v.x), hy = bf16_hi(v.y), hz = bf16_hi(v.z), hw = bf16_hi(v.w);
            uint2 hp = make_uint2(pack_bf16(hx, hy), pack_bf16(hz, hw));
            uint2 lp = make_uint2(pack_bf16(v.x - hx, v.y - hy), pack_bf16(v.z - hz, v.w - hw));
            *reinterpret_cast<uint2*>(smc + OFF_XHI + r * SROW + kq * 8) = hp;
            *reinterpret_cast<uint2*>(smc + OFF_XLO + r * SROW + kq * 8) = lp;
        }
        __syncthreads();

        float acc[4][4];
#pragma unroll
        for (int j = 0; j < 4; j++)
#pragma unroll
            for (int q = 0; q < 4; q++) acc[j][q] = 0.f;

        uint32_t ahb = su + OFF_XHI + a_off;
        uint32_t alb = su + OFF_XLO + a_off;
        uint32_t bhb = su + OFF_WHI + b_off;
        uint32_t blb = su + OFF_WLO + b_off;

#pragma unroll
        for (int ks = 0; ks < 16; ks++) {
            uint32_t ah0, ah1, ah2, ah3, al0, al1, al2, al3;
            ldsm_x4(ahb + ks * 32, ah0, ah1, ah2, ah3);
            ldsm_x4(alb + ks * 32, al0, al1, al2, al3);
#pragma unroll
            for (int j = 0; j < 2; j++) {
                uint32_t bh0, bh1, bh2, bh3, bl0, bl1, bl2, bl3;
                ldsm_x4(bhb + j * 16 * SROW + ks * 32, bh0, bh1, bh2, bh3);
                ldsm_x4(blb + j * 16 * SROW + ks * 32, bl0, bl1, bl2, bl3);
                mma_bf16(acc[2 * j],     ah0, ah1, ah2, ah3, bh0, bh1);
                mma_bf16(acc[2 * j + 1], ah0, ah1, ah2, ah3, bh2, bh3);
                mma_bf16(acc[2 * j],     al0, al1, al2, al3, bh0, bh1);
                mma_bf16(acc[2 * j + 1], al0, al1, al2, al3, bh2, bh3);
                mma_bf16(acc[2 * j],     ah0, ah1, ah2, ah3, bl0, bl1);
                mma_bf16(acc[2 * j + 1], ah0, ah1, ah2, ah3, bl2, bl3);
            }
        }

        int g = lane >> 2, tt = lane & 3;
        int r0g = row0 + wr * 16 + g;
        int r1g = r0g + 8;
        float di0 = (r0g < NN) ? g_dis[r0g] : 0.f;
        float di1 = (r1g < NN) ? g_dis[r1g] : 0.f;
#pragma unroll
        for (int j = 0; j < 4; j++) {
            int c = wc * 32 + j * 8 + 2 * tt;
            if (r0g < NN)
                *reinterpret_cast<__half2*>(g_hw1h + r0g * HID + c) =
                    __floats2half2_rn(di0 * acc[j][0], di0 * acc[j][1]);
            if (r1g < NN)
                *reinterpret_cast<__half2*>(g_hw1h + r1g * HID + c) =
                    __floats2half2_rn(di1 * acc[j][2], di1 * acc[j][3]);
        }
    }
}

// ------------------------- aggregation: warp per node (R13 exact loop shape) ---------
__device__ __forceinline__ float4 h4_to_f4(uint2 u) {
    __half2 a = *reinterpret_cast<__half2*>(&u.x);
    __half2 b = *reinterpret_cast<__half2*>(&u.y);
    float2 fa = __half22float2(a);
    float2 fb = __half22float2(b);
    return make_float4(fa.x, fa.y, fb.x, fb.y);
}

__global__ __launch_bounds__(256) void agg1_kernel(const float* __restrict__ b1) {
    int gw = (blockIdx.x * blockDim.x + threadIdx.x) >> 5;
    int lane = threadIdx.x & 31;
    if (gw >= NN) return;
    int beg = g_offsets[gw], end = g_offsets[gw + 1];
    const uint2* f2 = (const uint2*)g_hw1h;
    float4 acc = h4_to_f4(f2[gw * 32 + lane]);
    int p = beg;
    for (; p + 1 < end; p += 2) {
        int s0 = g_srclist[p], s1 = g_srclist[p + 1];
        float4 v0 = h4_to_f4(f2[s0 * 32 + lane]);
        float4 v1 = h4_to_f4(f2[s1 * 32 + lane]);
        acc.x += v0.x; acc.y += v0.y; acc.z += v0.z; acc.w += v0.w;
        acc.x += v1.x; acc.y += v1.y; acc.z += v1.z; acc.w += v1.w;
    }
    if (p < end) {
        float4 v = h4_to_f4(f2[g_srclist[p] * 32 + lane]);
        acc.x += v.x; acc.y += v.y; acc.z += v.z; acc.w += v.w;
    }
    float di = g_dis[gw];
    float4 b = ((const float4*)b1)[lane];
    float rx = di * fmaxf(fmaf(di, acc.x, b.x), 0.f);
    float ry = di * fmaxf(fmaf(di, acc.y, b.y), 0.f);
    float rz = di * fmaxf(fmaf(di, acc.z, b.z), 0.f);
    float rw = di * fmaxf(fmaf(di, acc.w, b.w), 0.f);
    uint2 o;
    __half2 h0 = __floats2half2_rn(rx, ry);
    __half2 h1 = __floats2half2_rn(rz, rw);
    o.x = *reinterpret_cast<uint32_t*>(&h0);
    o.y = *reinterpret_cast<uint32_t*>(&h1);
    ((uint2*)g_hsh)[gw * 32 + lane] = o;
}

__global__ __launch_bounds__(256) void agg2_kernel() {
    int gw = (blockIdx.x * blockDim.x + threadIdx.x) >> 5;
    int lane = threadIdx.x & 31;
    if (gw >= NN) return;
    int beg = g_offsets[gw], end = g_offsets[gw + 1];
    const uint2* f2 = (const uint2*)g_hsh;
    float4 acc = h4_to_f4(f2[gw * 32 + lane]);
    int p = beg;
    for (; p + 1 < end; p += 2) {
        int s0 = g_srclist[p], s1 = g_srclist[p + 1];
        float4 v0 = h4_to_f4(f2[s0 * 32 + lane]);
        float4 v1 = h4_to_f4(f2[s1 * 32 + lane]);
        acc.x += v0.x; acc.y += v0.y; acc.z += v0.z; acc.w += v0.w;
        acc.x += v1.x; acc.y += v1.y; acc.z += v1.z; acc.w += v1.w;
    }
    if (p < end) {
        float4 v = h4_to_f4(f2[g_srclist[p] * 32 + lane]);
        acc.x += v.x; acc.y += v.y; acc.z += v.z; acc.w += v.w;
    }
    float di = g_dis[gw];
    uint2 o;
    __half2 h0 = __floats2half2_rn(di * acc.x, di * acc.y);
    __half2 h1 = __floats2half2_rn(di * acc.z, di * acc.w);
    o.x = *reinterpret_cast<uint32_t*>(&h0);
    o.y = *reinterpret_cast<uint32_t*>(&h1);
    ((uint2*)g_gh)[gw * 32 + lane] = o;
}

// ------------------------- GEMM2 via mma.sync bf16 hi/lo (input fp16) ----------------
#define SROW2 272
#define OFF2_WHI 0
#define OFF2_WLO 34816
#define OFF2_XHI 69632
#define OFF2_XLO 87040
#define OFF2_BIAS 104448
#define G2_SMEM 104960

__global__ __launch_bounds__(256, 2)
void gemm2_mma_kernel(const float* __restrict__ Wmu, const float* __restrict__ bmu,
                      const float* __restrict__ Wlv, const float* __restrict__ blv,
                      float* __restrict__ out) {
    extern __shared__ char smc[];
    uint32_t su = smem_u32(smc);
    int tid = threadIdx.x, lane = tid & 31, warp = tid >> 5;
    int wr = warp & 3;
    int wc = warp >> 2;

#pragma unroll
    for (int it = 0; it < 16; it++) {
        int idx = it * 256 + tid;
        int o = idx >> 5, kq = idx & 31;
        float4 v = (o < OUT_DIM) ? ((const float4*)Wmu)[o * 32 + kq]
                                 : ((const float4*)Wlv)[(o - OUT_DIM) * 32 + kq];
        float hx = bf16_hi(v.x), hy = bf16_hi(v.y), hz = bf16_hi(v.z), hw = bf16_hi(v.w);
        uint2 hp = make_uint2(pack_bf16(hx, hy), pack_bf16(hz, hw));
        uint2 lp = make_uint2(pack_bf16(v.x - hx, v.y - hy), pack_bf16(v.z - hz, v.w - hw));
        *reinterpret_cast<uint2*>(smc + OFF2_WHI + o * SROW2 + kq * 8) = hp;
        *reinterpret_cast<uint2*>(smc + OFF2_WLO + o * SROW2 + kq * 8) = lp;
    }
    if (tid < HID) {
        float b = (tid < OUT_DIM) ? bmu[tid] : blv[tid - OUT_DIM];
        *reinterpret_cast<float*>(smc + OFF2_BIAS + tid * 4) = b;
    }

    uint32_t a_off = (uint32_t)((wr * 16 + (lane & 15)) * SROW2 + ((lane >> 4) << 4));
    uint32_t b_row = (uint32_t)((lane & 7) + ((lane >> 4) << 3));
    uint32_t b_off = (uint32_t)((wc * 64 + b_row) * SROW2 + (((lane >> 3) & 1) << 4));

    const int NT = (NN + 63) / 64;
    for (int t = blockIdx.x; t < NT; t += gridDim.x) {
        int row0 = t * 64;
        __syncthreads();
        // stage x from fp16 g_gh: idx -> row r (0..63), kq (0..31 groups of 4 halves)
#pragma unroll
        for (int it = 0; it < 8; it++) {
            int idx = it * 256 + tid;
            int r = idx >> 5, kq = idx & 31;
            int grow = row0 + r;
            float4 v = make_float4(0.f, 0.f, 0.f, 0.f);
            if (grow < NN) v = h4_to_f4(((const uint2*)g_gh)[grow * 32 + kq]);
            float hx = bf16_hi(v.x), hy = bf16_hi(v.y), hz = bf16_hi(v.z), hw = bf16_hi(v.w);
            uint2 hp = make_uint2(pack_bf16(hx, hy), pack_bf16(hz, hw));
            uint2 lp = make_uint2(pack_bf16(v.x - hx, v.y - hy), pack_bf16(v.z - hz, v.w - hw));
            *reinterpret_cast<uint2*>(smc + OFF2_XHI + r * SROW2 + kq * 8) = hp;
            *reinterpret_cast<uint2*>(smc + OFF2_XLO + r * SROW2 + kq * 8) = lp;
        }
        __syncthreads();

        float acc[8][4];
#pragma unroll
        for (int j = 0; j < 8; j++)
#pragma unroll
            for (int q = 0; q < 4; q++) acc[j][q] = 0.f;

        uint32_t ahb = su + OFF2_XHI + a_off;
        uint32_t alb = su + OFF2_XLO + a_off;
        uint32_t bhb = su + OFF2_WHI + b_off;
        uint32_t blb = su + OFF2_WLO + b_off;

#pragma unroll
        for (int ks = 0; ks < 8; ks++) {
            uint32_t ah0, ah1, ah2, ah3, al0, al1, al2, al3;
            ldsm_x4(ahb + ks * 32, ah0, ah1, ah2, ah3);
            ldsm_x4(alb + ks * 32, al0, al1, al2, al3);
#pragma unroll
            for (int j = 0; j < 4; j++) {
                uint32_t bh0, bh1, bh2, bh3, bl0, bl1, bl2, bl3;
                ldsm_x4(bhb + j * 16 * SROW2 + ks * 32, bh0, bh1, bh2, bh3);
                ldsm_x4(blb + j * 16 * SROW2 + ks * 32, bl0, bl1, bl2, bl3);
                mma_bf16(acc[2 * j],     ah0, ah1, ah2, ah3, bh0, bh1);
                mma_bf16(acc[2 * j + 1], ah0, ah1, ah2, ah3, bh2, bh3);
                mma_bf16(acc[2 * j],     al0, al1, al2, al3, bh0, bh1);
                mma_bf16(acc[2 * j + 1], al0, al1, al2, al3, bh2, bh3);
                mma_bf16(acc[2 * j],     ah0, ah1, ah2, ah3, bl0, bl1);
                mma_bf16(acc[2 * j + 1], ah0, ah1, ah2, ah3, bl2, bl3);
            }
        }

        int g = lane >> 2, tt = lane & 3;
        int r0g = row0 + wr * 16 + g;
        int r1g = r0g + 8;
        float* obase = (wc == 0) ? out : (out + NOFF);
#pragma unroll
        for (int j = 0; j < 8; j++) {
            int cl = j * 8 + 2 * tt;
            float2 bv = *reinterpret_cast<float2*>(smc + OFF2_BIAS + (wc * 64 + cl) * 4);
            if (r0g < NN)
                *reinterpret_cast<float2*>(obase + r0g * OUT_DIM + cl) =
                    make_float2(acc[j][0] + bv.x, acc[j][1] + bv.y);
            if (r1g < NN)
                *reinterpret_cast<float2*>(obase + r1g * OUT_DIM + cl) =
                    make_float2(acc[j][2] + bv.x, acc[j][3] + bv.y);
        }
    }
}

// ------------------------- launch (R13 order, proven) -------------------------
extern "C" void kernel_launch(void* const* d_in, const int* in_sizes, int n_in,
                              void* d_out, int out_size) {
    const float* x   = (const float*)d_in[0];
    const void*  ei  = d_in[1];
    const float* W1  = (const float*)d_in[2];
    const float* b1  = (const float*)d_in[3];
    const float* Wmu = (const float*)d_in[4];
    const float* bmu = (const float*)d_in[5];
    const float* Wlv = (const float*)d_in[6];
    const float* blv = (const float*)d_in[7];
    float* out = (float*)d_out;

    void* p_count;  cudaGetSymbolAddress(&p_count, g_count);
    void* p_cursor; cudaGetSymbolAddress(&p_cursor, g_cursor);

    cudaFuncSetAttribute(gemm1_mma_kernel, cudaFuncAttributeMaxDynamicSharedMemorySize, G1_SMEM);
    cudaFuncSetAttribute(gemm2_mma_kernel, cudaFuncAttributeMaxDynamicSharedMemorySize, G2_SMEM);

    cudaMemsetAsync(p_count, 0, NN * sizeof(int));
    cudaMemsetAsync(p_cursor, 0, NN * sizeof(int));

    detect_kernel<<<1, 32>>>(ei);                                // #1
    convert_hist_kernel<<<(EE + 255) / 256, 256>>>(ei);          // #2
    dis_kernel<<<(NN + 255) / 256, 256>>>();                     // #3

    gemm1_mma_kernel<<<148, 512, G1_SMEM>>>(x, W1);              // #4  <- profiled

    scan_kernel<<<1, 1024>>>();                                  // #5
    scatter_kernel<<<(EE + 255) / 256, 256>>>();                 // #6

    int agg_blocks = (NN * 32 + 255) / 256;
    agg1_kernel<<<agg_blocks, 256>>>(b1);                        // #7
    agg2_kernel<<<agg_blocks, 256>>>();                          // #8

    gemm2_mma_kernel<<<296, 256, G2_SMEM>>>(Wmu, bmu, Wlv, blv, out);  // #9
}